// round 6
// baseline (speedup 1.0000x reference)
#include <cuda_runtime.h>
#include <cstdint>

// Problem constants
#define BB 64      // batch
#define TT 512     // seq len
#define DD 256     // input dim
#define UU 512     // units
#define MM 64      // memory slots
#define NN 2112    // 4*U + M
#define KK 768     // D + U

#define NBLK 132   // 66 n-stripes x 2 batch-halves

// dynamic smem layout (float offsets)
//  s_W   : [768][32]     24576 f  (persistent weight stripe)
//  s_a   : 2 x [128][36]  9216 f  (A double buffer; buf0 aliased by s_p u64[2304])
//  s_mem : [64][256]     16384 f  (block-private shift-register memory)
#define SA_STRIDE 36
#define SA_BUF 4608
#define SA_OFF 24576
#define SM_OFF 33792
#define SMEM_FLOATS 50176
#define SMEM_BYTES (SMEM_FLOATS * 4)   // 200704 B

// -------- device scratch (no allocations allowed) --------
__device__ float g_W[KK * NN];
__device__ float g_b[NN];
__device__ float g_h[BB * UU];
__device__ float g_z[BB * NN];
__device__ unsigned g_count = 0;
__device__ unsigned g_epoch = 0;

// =====================================================================
// Init: pack W/U/b into [768 x 2112], zero h.
// =====================================================================
__global__ void init_kernel(
    const float* __restrict__ Wi, const float* __restrict__ Ui, const float* __restrict__ bi,
    const float* __restrict__ Wf, const float* __restrict__ Uf, const float* __restrict__ bf,
    const float* __restrict__ Wo, const float* __restrict__ Uo, const float* __restrict__ bo,
    const float* __restrict__ Wc, const float* __restrict__ Uc, const float* __restrict__ bc,
    const float* __restrict__ We, const float* __restrict__ Ue, const float* __restrict__ be)
{
    int stride = gridDim.x * blockDim.x;
    int t0 = blockIdx.x * blockDim.x + threadIdx.x;

    for (int i = t0; i < KK * NN; i += stride) {
        int k = i / NN;
        int n = i - k * NN;
        float v;
        if (n < 4 * UU) {
            int g = n >> 9;
            int col = n & (UU - 1);
            const float* s;
            if (k < DD) {
                s = (g == 0) ? Wi : (g == 1) ? Wf : (g == 2) ? Wo : Wc;
                v = s[k * UU + col];
            } else {
                s = (g == 0) ? Ui : (g == 1) ? Uf : (g == 2) ? Uo : Uc;
                v = s[(k - DD) * UU + col];
            }
        } else {
            int col = n - 4 * UU;
            v = (k < DD) ? We[k * MM + col] : Ue[(k - DD) * MM + col];
        }
        g_W[i] = v;
    }
    for (int i = t0; i < NN; i += stride) {
        float v;
        if (i < 4 * UU) {
            int g = i >> 9;
            int col = i & (UU - 1);
            v = (g == 0) ? bi[col] : (g == 1) ? bf[col] : (g == 2) ? bo[col] : bc[col];
        } else {
            v = be[i - 4 * UU];
        }
        g_b[i] = v;
    }
    for (int i = t0; i < BB * UU; i += stride) g_h[i] = 0.0f;
}

// =====================================================================
// Grid-wide software barrier: release-atomic arrival, acquire-load spin.
// No SC fence (no CCTL.IVALL L1 flush), no SYS-scope volatile polling.
// =====================================================================
__device__ __forceinline__ void grid_barrier(unsigned* my_epoch)
{
    __syncthreads();
    if (threadIdx.x == 0) {
        unsigned target = *my_epoch + 1u;
        unsigned v;
        asm volatile("atom.release.gpu.global.add.u32 %0, [%1], 1;"
                     : "=r"(v) : "l"(&g_count) : "memory");
        if (v == NBLK - 1) {
            unsigned zero = 0;
            asm volatile("st.relaxed.gpu.global.u32 [%0], %1;"
                         :: "l"(&g_count), "r"(zero) : "memory");
            asm volatile("st.release.gpu.global.u32 [%0], %1;"
                         :: "l"(&g_epoch), "r"(target) : "memory");
        } else {
            unsigned e;
            do {
                asm volatile("ld.acquire.gpu.global.u32 %0, [%1];"
                             : "=r"(e) : "l"(&g_epoch) : "memory");
            } while ((int)(e - target) < 0);
        }
        *my_epoch = target;
    }
    __syncthreads();
}

__device__ __forceinline__ void ffma2(unsigned long long& acc,
                                      unsigned long long a2,
                                      unsigned long long b2)
{
    asm("fma.rn.f32x2 %0, %1, %2, %0;" : "+l"(acc) : "l"(a2), "l"(b2));
}

__device__ __forceinline__ float rcpa(float x)
{
    float r; asm("rcp.approx.f32 %0, %1;" : "=f"(r) : "f"(x)); return r;
}
__device__ __forceinline__ float fsig(float x)   // sigmoid, ~1e-6 rel err
{
    return rcpa(1.0f + __expf(-x));
}
__device__ __forceinline__ float ftanh(float x)  // 2*sigmoid(2x)-1
{
    return 2.0f * rcpa(1.0f + __expf(-2.0f * x)) - 1.0f;
}

// =====================================================================
// Persistent kernel: 512 x { GEMM -> barrier -> pointwise -> barrier }.
// Block = (n-stripe, batch-half): z[32m x 32n] over K=768.
// Warp = (kg 0..3, mh 0..1): 16m x 32n over 192 k. Lane tile 4m x 4n,
// m-paired FFMA2 (A float4 reg pair used directly as f32x2 operand).
// =====================================================================
__global__ __launch_bounds__(256, 1) void xlstm_persistent(
    const float* __restrict__ x, float* __restrict__ out)
{
    extern __shared__ float smem[];
    float* s_W  = smem;
    float* s_aF = smem + SA_OFF;
    unsigned long long* s_p  = (unsigned long long*)(smem + SA_OFF); // alias buf0
    float*              s_pf = (float*)(smem + SA_OFF);
    float* s_mem = smem + SM_OFF;
    __shared__ float s_e[MM];
    __shared__ float s_ew[MM];

    const int tid  = threadIdx.x;
    const int lane = tid & 31;
    const int warp = tid >> 5;
    const int blk  = blockIdx.x;
    const int n0   = (blk >> 1) * 32;
    const int m0   = (blk & 1) * 32;

    // compute-role decomposition
    const int kg  = warp >> 1;            // 0..3 (k-group of 192)
    const int mh  = warp & 1;             // 0..1 (m-half of 16)
    const int mq  = lane >> 3;            // 0..3 (4-row group in m-half)
    const int nq8 = lane & 7;             // 0..7 (4-col group)

    // staging-role decomposition: warp stages kg_s's (khalf) 16 k-slots
    const int kg_s   = warp >> 1;
    const int khalf  = (warp & 1) * 16;
    const int sm     = lane >> 2;         // m base 0..7 (rows sm, sm+8, sm+16, sm+24)
    const int sk     = (lane & 3) * 4;    // k offset 0,4,8,12

    // ---- load W stripe into smem once (persistent across all 512 steps)
#pragma unroll 4
    for (int q = 0; q < 96; ++q) {
        int i = tid + q * 256;            // 0..24575
        int k = i >> 5, n = i & 31;
        s_W[i] = g_W[k * NN + n0 + n];
    }
    // ---- zero block-private memory
    for (int i = tid; i < MM * 256; i += 256) s_mem[i] = 0.0f;

    unsigned my_epoch = 0;
    if (tid == 0) {
        asm volatile("ld.acquire.gpu.global.u32 %0, [%1];"
                     : "=r"(my_epoch) : "l"(&g_epoch) : "memory");
    }
    __syncthreads();

#define LOAD_CHUNK(cc)                                                        \
    {                                                                         \
        int kb = kg_s * 192 + (cc) * 32 + khalf + sk;                         \
        if (kb < DD) {                                                        \
            const float* bp = x + (size_t)(m0 + sm) * (TT * DD)               \
                                + (size_t)t * DD + kb;                        \
            v0 = *(const float4*)(bp);                                        \
            v1 = *(const float4*)(bp + (size_t)8  * (TT * DD));               \
            v2 = *(const float4*)(bp + (size_t)16 * (TT * DD));               \
            v3 = *(const float4*)(bp + (size_t)24 * (TT * DD));               \
        } else {                                                              \
            const float* hp = g_h + (m0 + sm) * UU + (kb - DD);               \
            v0 = __ldcg((const float4*)(hp));                                 \
            v1 = __ldcg((const float4*)(hp + 8  * UU));                       \
            v2 = __ldcg((const float4*)(hp + 16 * UU));                       \
            v3 = __ldcg((const float4*)(hp + 24 * UU));                       \
        }                                                                     \
    }

#define STORE_CHUNK(bsel)                                                     \
    {                                                                         \
        float* d = s_aF + (bsel) * SA_BUF                                     \
                 + (kg_s * 32 + khalf + sk) * SA_STRIDE + sm;                 \
        d[0 * SA_STRIDE + 0]  = v0.x; d[1 * SA_STRIDE + 0]  = v0.y;           \
        d[2 * SA_STRIDE + 0]  = v0.z; d[3 * SA_STRIDE + 0]  = v0.w;           \
        d[0 * SA_STRIDE + 8]  = v1.x; d[1 * SA_STRIDE + 8]  = v1.y;           \
        d[2 * SA_STRIDE + 8]  = v1.z; d[3 * SA_STRIDE + 8]  = v1.w;           \
        d[0 * SA_STRIDE + 16] = v2.x; d[1 * SA_STRIDE + 16] = v2.y;           \
        d[2 * SA_STRIDE + 16] = v2.z; d[3 * SA_STRIDE + 16] = v2.w;           \
        d[0 * SA_STRIDE + 24] = v3.x; d[1 * SA_STRIDE + 24] = v3.y;           \
        d[2 * SA_STRIDE + 24] = v3.z; d[3 * SA_STRIDE + 24] = v3.w;           \
    }

    for (int t = 0; t < TT; ++t) {
        // ============================ GEMM ============================
        unsigned long long acc[8];
#pragma unroll
        for (int q = 0; q < 8; ++q) acc[q] = 0ull;

        float4 v0, v1, v2, v3;
        LOAD_CHUNK(0)
        STORE_CHUNK(0)
        __syncthreads();

#pragma unroll 1
        for (int c = 0; c < 6; ++c) {
            const int cur = c & 1;
            if (c < 5) LOAD_CHUNK(c + 1)

            {
                const float* sap = s_aF + cur * SA_BUF
                                 + (kg * 32) * SA_STRIDE + mh * 16 + 4 * mq;
                const float* swp = s_W + (kg * 192 + c * 32) * 32 + 4 * nq8;
#pragma unroll
                for (int kk = 0; kk < 32; ++kk) {
                    ulonglong2 av = *(const ulonglong2*)(sap + kk * SA_STRIDE);
                    float4 bv = *(const float4*)(swp + kk * 32);
                    unsigned long long b0, b1, b2, b3;
                    asm("mov.b64 %0, {%1, %1};" : "=l"(b0) : "f"(bv.x));
                    asm("mov.b64 %0, {%1, %1};" : "=l"(b1) : "f"(bv.y));
                    asm("mov.b64 %0, {%1, %1};" : "=l"(b2) : "f"(bv.z));
                    asm("mov.b64 %0, {%1, %1};" : "=l"(b3) : "f"(bv.w));
                    ffma2(acc[0], av.x, b0); ffma2(acc[1], av.y, b0);
                    ffma2(acc[2], av.x, b1); ffma2(acc[3], av.y, b1);
                    ffma2(acc[4], av.x, b2); ffma2(acc[5], av.y, b2);
                    ffma2(acc[6], av.x, b3); ffma2(acc[7], av.y, b3);
                }
            }

            if (c < 5) STORE_CHUNK(1 - cur)
            __syncthreads();
        }

        // ---- cross-kg reduction: per-thread padded region (2-way max)
        {
            unsigned long long* pp = s_p + (size_t)tid * 9;
#pragma unroll
            for (int q = 0; q < 8; ++q) pp[q] = acc[q];
        }
        __syncthreads();
        // readers: 4 outputs/thread; acc[2j+p].{lo,hi} = rows (.. +2p, +2p+1), col 4nq8+j
#pragma unroll
        for (int q2 = 0; q2 < 4; ++q2) {
            int o  = tid + q2 * 256;      // 0..1023
            int m  = o >> 5;              // 0..31
            int n  = o & 31;
            int mw   = m & 15;
            int lsrc = (mw >> 2) * 8 + (n >> 2);
            int qidx = 2 * (n & 3) + ((mw >> 1) & 1);
            int fo   = mw & 1;
            int wb   = (m >> 4);          // mh of source warp
            float s = g_b[n0 + n];
#pragma unroll
            for (int kgs = 0; kgs < 4; ++kgs) {
                int widx = ((kgs * 2 + wb) * 32 + lsrc) * 9 + qidx;
                s += s_pf[widx * 2 + fo];
            }
            g_z[(size_t)(m0 + m) * NN + n0 + n] = s;
        }

        grid_barrier(&my_epoch);

        // ========================== pointwise =========================
        if (blk < 2 * BB) {
            const int b    = blk >> 1;
            const int half = blk & 1;

            if (tid < 32) {
                float z0 = __ldcg(&g_z[b * NN + 4 * UU + tid]);
                float z1 = __ldcg(&g_z[b * NN + 4 * UU + 32 + tid]);
                float mx = fmaxf(z0, z1);
#pragma unroll
                for (int o = 16; o > 0; o >>= 1)
                    mx = fmaxf(mx, __shfl_xor_sync(0xffffffffu, mx, o));
                float e0 = __expf(z0 - mx);
                float e1 = __expf(z1 - mx);
                float sm2 = e0 + e1;
#pragma unroll
                for (int o = 16; o > 0; o >>= 1)
                    sm2 += __shfl_xor_sync(0xffffffffu, sm2, o);
                float inv = rcpa(sm2);
                s_e[tid]      = e0 * inv;
                s_e[tid + 32] = e1 * inv;
            }
            __syncthreads();
            // physical slot s holds c from step t'=s mod 64; age m = t-1-t'
            if (tid < MM) s_ew[tid] = s_e[(t - 1 - tid) & (MM - 1)];
            __syncthreads();

            const int u  = half * 256 + tid;
            const int zb = b * NN;
            float zi = __ldcg(&g_z[zb + u]);
            float zf = __ldcg(&g_z[zb + UU + u]);
            float zo = __ldcg(&g_z[zb + 2 * UU + u]);
            float zc = __ldcg(&g_z[zb + 3 * UU + u]);

            float gi = fsig(zi);
            float gf = fsig(zf);
            float go = fsig(zo);
            float ct = ftanh(zc);

            const float* mb = s_mem + tid;
            float c0 = 0.f, c1 = 0.f, c2 = 0.f, c3 = 0.f;
#pragma unroll
            for (int s = 0; s < MM; s += 4) {
                c0 += s_ew[s + 0] * mb[(s + 0) * 256];
                c1 += s_ew[s + 1] * mb[(s + 1) * 256];
                c2 += s_ew[s + 2] * mb[(s + 2) * 256];
                c3 += s_ew[s + 3] * mb[(s + 3) * 256];
            }
            float contrib = (c0 + c1) + (c2 + c3);

            float cc = gf * contrib + gi * ct;
            float hh = go * ftanh(cc);

            s_mem[(t & (MM - 1)) * 256 + tid] = cc;   // overwrite oldest slot
            g_h[b * UU + u] = hh;
            out[(size_t)b * (TT * UU) + (size_t)t * UU + u] = hh;
        }

        grid_barrier(&my_epoch);
    }
#undef LOAD_CHUNK
#undef STORE_CHUNK
}

// =====================================================================
// Launch: 2 graph nodes. No allocations, graph-capturable.
// =====================================================================
extern "C" void kernel_launch(void* const* d_in, const int* in_sizes, int n_in,
                              void* d_out, int out_size)
{
    (void)in_sizes; (void)n_in; (void)out_size;
    const float* x  = (const float*)d_in[0];
    const float* Wi = (const float*)d_in[1];
    const float* Ui = (const float*)d_in[2];
    const float* bi = (const float*)d_in[3];
    const float* Wf = (const float*)d_in[4];
    const float* Uf = (const float*)d_in[5];
    const float* bf = (const float*)d_in[6];
    const float* Wo = (const float*)d_in[7];
    const float* Uo = (const float*)d_in[8];
    const float* bo = (const float*)d_in[9];
    const float* Wc = (const float*)d_in[10];
    const float* Uc = (const float*)d_in[11];
    const float* bc = (const float*)d_in[12];
    const float* We = (const float*)d_in[13];
    const float* Ue = (const float*)d_in[14];
    const float* be = (const float*)d_in[15];
    float* out = (float*)d_out;

    cudaFuncSetAttribute(xlstm_persistent,
                         cudaFuncAttributeMaxDynamicSharedMemorySize, SMEM_BYTES);

    init_kernel<<<1024, 256>>>(Wi, Ui, bi, Wf, Uf, bf, Wo, Uo, bo,
                               Wc, Uc, bc, We, Ue, be);
    xlstm_persistent<<<NBLK, 256, SMEM_BYTES>>>(x, out);
}